// round 15
// baseline (speedup 1.0000x reference)
#include <cuda_runtime.h>
#include <cuda_fp16.h>
#include <cstdint>

// ===========================================================================
// VectorQuantizer on GB300 (sm_103 family): single-pass fp16 distance GEMM
// (fp32 accum) + hierarchical exact top-2 argmin, exact fp32 fixup.
// R13: 8 warps in 2x4 grid (warp tile 64x32) -> 25% less LDSM traffic/MMA
// (A/B cross-warp redundancy cut), R11 double-buffered mainloop retained.
// ===========================================================================

#define NROWS    32768
#define DDIM     256
#define KCODES   8192
#define ROWTILE  128
#define NCTAS    (NROWS / ROWTILE)      // 256
#define NTILES   (KCODES / 128)         // 64
#define NCH      (NTILES * 2)           // 128 E chunks (128 k each)
#define THREADS  256
#define FIXWARPS 8
#define FIXBLOCKS (NROWS / FIXWARPS)    // 4096

// SMEM layout (bytes): X @0 (67584, stride 528); E ring @67584 (3 x 34816,
// stride 272); enorm @172032 (32768). total 204800
#define X_OFF     0
#define E_OFF     67584
#define ESTAGE    34816
#define EN_OFF    172032
#define SMEM_DYN  204800
#define SX        528
#define SE        272

__device__ unsigned short g_Xf[NROWS * DDIM];
__device__ unsigned short g_Ef[KCODES * DDIM];
__device__ float g_enorm[KCODES];
__device__ int   g_i1[NROWS];
__device__ int   g_i2[NROWS];
__device__ float g_part[FIXBLOCKS];

// ------------------------------ PTX helpers ---------------------------------
__device__ __forceinline__ uint32_t smem_u32(const void* p) {
    uint32_t a;
    asm("{ .reg .u64 t; cvta.to.shared.u64 t, %1; cvt.u32.u64 %0, t; }"
        : "=r"(a) : "l"(p));
    return a;
}

__device__ __forceinline__ void ldsm4(uint32_t* r, uint32_t addr) {
    asm volatile("ldmatrix.sync.aligned.m8n8.x4.shared.b16 {%0,%1,%2,%3}, [%4];"
                 : "=r"(r[0]), "=r"(r[1]), "=r"(r[2]), "=r"(r[3]) : "r"(addr));
}

__device__ __forceinline__ void mma_f16(float* d, const uint32_t* a,
                                        const uint32_t* b) {
    asm volatile(
        "mma.sync.aligned.m16n8k16.row.col.f32.f16.f16.f32 "
        "{%0,%1,%2,%3}, {%4,%5,%6,%7}, {%8,%9}, {%0,%1,%2,%3};"
        : "+f"(d[0]), "+f"(d[1]), "+f"(d[2]), "+f"(d[3])
        : "r"(a[0]), "r"(a[1]), "r"(a[2]), "r"(a[3]), "r"(b[0]), "r"(b[1]));
}

__device__ __forceinline__ void cpasync16(uint32_t dst, const void* src) {
    asm volatile("cp.async.cg.shared.global [%0], [%1], 16;"
                 :: "r"(dst), "l"(src));
}
#define CP_COMMIT() asm volatile("cp.async.commit_group;" ::: "memory")
#define CP_WAIT0()  asm volatile("cp.async.wait_group 0;" ::: "memory")
#define CP_WAIT1()  asm volatile("cp.async.wait_group 1;" ::: "memory")

// EXACT branchless top-2 insert (fp32 compares, separate index).
__device__ __forceinline__ void t2x(float s, int i,
                                    float& V1, int& I1, float& V2, int& I2) {
    bool lt1 = s < V1;
    bool lt2 = s < V2;
    float nV2 = lt1 ? V1 : (lt2 ? s : V2);
    int   nI2 = lt1 ? I1 : (lt2 ? i : I2);
    V1 = lt1 ? s : V1;
    I1 = lt1 ? i : I1;
    V2 = nV2; I2 = nI2;
}

// tie-aware insert for final merges (prefers lower index on equal value)
__device__ __forceinline__ void t2_ins(float& v1, int& i1, float& v2, int& i2,
                                       float v, int i) {
    if (v < v1 || (v == v1 && i < i1)) { v2 = v1; i2 = i1; v1 = v; i1 = i; }
    else if (v < v2 || (v == v2 && i < i2)) { v2 = v; i2 = i; }
}

// ------------------------------- prep kernels -------------------------------
__global__ void vq_conv_x(const float4* __restrict__ in, int n4) {
    int i = blockIdx.x * blockDim.x + threadIdx.x;
    if (i >= n4) return;
    float4 v = in[i];
    float f[4] = {fminf(fmaxf(v.x, -1.f), 1.f), fminf(fmaxf(v.y, -1.f), 1.f),
                  fminf(fmaxf(v.z, -1.f), 1.f), fminf(fmaxf(v.w, -1.f), 1.f)};
    unsigned short h[4];
#pragma unroll
    for (int j = 0; j < 4; j++) h[j] = __half_as_ushort(__float2half_rn(f[j]));
    ((uint2*)g_Xf)[i] = make_uint2(h[0] | ((uint32_t)h[1] << 16),
                                   h[2] | ((uint32_t)h[3] << 16));
}

__global__ void vq_conv_e(const float4* __restrict__ in, int n4) {
    int i = blockIdx.x * blockDim.x + threadIdx.x;
    if (i >= n4) return;
    float4 v = in[i];
    float f[4] = {v.x, v.y, v.z, v.w};
    unsigned short h[4];
#pragma unroll
    for (int j = 0; j < 4; j++) h[j] = __half_as_ushort(__float2half_rn(f[j]));
    ((uint2*)g_Ef)[i] = make_uint2(h[0] | ((uint32_t)h[1] << 16),
                                   h[2] | ((uint32_t)h[3] << 16));
}

__global__ void vq_enorm_kernel(const float* __restrict__ emb, int K) {
    int k = blockIdx.x * blockDim.x + threadIdx.x;
    if (k >= K) return;
    const float4* r = (const float4*)(emb + (size_t)k * DDIM);
    float s = 0.0f;
#pragma unroll
    for (int i = 0; i < DDIM / 4; i++) {
        float4 v = r[i];
        s += v.x * v.x + v.y * v.y + v.z * v.z + v.w * v.w;
    }
    g_enorm[k] = s;
}

// --------------------------------- main kernel ------------------------------
__global__ __launch_bounds__(THREADS, 1)
void vq_main_kernel() {
    extern __shared__ char sm[];
    const uint32_t smB = smem_u32(sm);

    const int tid   = threadIdx.x;
    const int lane  = tid & 31;
    const int wid   = tid >> 5;
    const int warp_m = wid & 1;         // 0..1 (64 rows each)
    const int warp_n = wid >> 1;        // 0..3 (32 codes each)
    const int l2    = lane & 3;
    const int row0  = blockIdx.x * ROWTILE;

    // ---- resident X tile + enorm into smem ----
    {
        const uint4* px = (const uint4*)g_Xf + (size_t)row0 * 32;
        for (int i = tid; i < 4096; i += THREADS) {
            int r = i >> 5, q = i & 31;
            *(uint4*)(sm + X_OFF + r * SX + q * 16) = px[r * 32 + q];
        }
        const float4* pe = (const float4*)g_enorm;
        for (int i = tid; i < 2048; i += THREADS)
            *(float4*)(sm + EN_OFF + i * 16) = pe[i];
    }

    // ---- cp.async E chunk (128 codes x 128 k fp16 = 32KB = 2048 uint4) ----
    auto issueE = [&](int stage, int chunk) {
        int t = chunk >> 1, kc = chunk & 1;
#pragma unroll
        for (int j = 0; j < 8; j++) {
            int i = tid + j * THREADS;            // 0..2047
            int r = i >> 4, q = i & 15;
            size_t soff = ((size_t)(t * 128 + r) * DDIM + kc * 128 + q * 8) * 2;
            uint32_t dst = smB + E_OFF + stage * ESTAGE + r * SE + q * 16;
            cpasync16(dst, (const char*)g_Ef + soff);
        }
        CP_COMMIT();
    };

    issueE(0, 0);
    issueE(1, 1);

    const uint32_t aOff = (uint32_t)(warp_m * 64 + (lane & 15)) * SX
                        + ((lane >> 4) << 4);
    const uint32_t bOff = (uint32_t)(warp_n * 32 + (lane & 7) + ((lane >> 4) << 3)) * SE
                        + (((lane >> 3) & 1) << 4);

    float acc[4][4][4];               // [mt][nt][frag]
    float V1[8], V2[8];
    int   I1[8], I2[8];
#pragma unroll
    for (int r = 0; r < 8; r++) {
        V1[r] = 3.4e38f; V2[r] = 3.4e38f; I1[r] = 0; I2[r] = 0;
    }

    uint32_t ah[2][4][4];             // [buf][mt][frag]
    uint32_t bf[2][4][2];             // [buf][nt][frag]

    int stage = 0;
    for (int t = 0; t < NTILES; ++t) {
#pragma unroll
        for (int mt = 0; mt < 4; mt++)
#pragma unroll
            for (int nt = 0; nt < 4; nt++)
#pragma unroll
                for (int rr = 0; rr < 4; rr++) acc[mt][nt][rr] = 0.f;

        for (int kc = 0; kc < 2; ++kc) {
            int idx = t * 2 + kc;
            if (idx + 1 < NCH) { CP_WAIT1(); } else { CP_WAIT0(); }
            __syncthreads();
            if (idx + 2 < NCH) {
                int s2 = stage + 2; if (s2 >= 3) s2 -= 3;
                issueE(s2, idx + 2);
            }

            const uint32_t eB = smB + E_OFF + stage * ESTAGE;
            stage = (stage == 2) ? 0 : stage + 1;
            const uint32_t akb0 = (uint32_t)(kc * 128) * 2;

            // preload ks=0 fragments into buf 0
#pragma unroll
            for (int mt = 0; mt < 4; mt++)
                ldsm4(ah[0][mt], smB + X_OFF + aOff + mt * (16 * SX) + akb0);
#pragma unroll
            for (int ntp = 0; ntp < 2; ntp++) {
                uint32_t r4[4];
                ldsm4(r4, eB + bOff + ntp * (16 * SE));
                bf[0][ntp * 2][0] = r4[0]; bf[0][ntp * 2][1] = r4[1];
                bf[0][ntp * 2 + 1][0] = r4[2]; bf[0][ntp * 2 + 1][1] = r4[3];
            }

#pragma unroll
            for (int ks = 0; ks < 8; ++ks) {
                const int cur = ks & 1, nxt = cur ^ 1;
                if (ks < 7) {
                    const uint32_t akb = akb0 + (uint32_t)(ks + 1) * 32;
#pragma unroll
                    for (int mt = 0; mt < 4; mt++)
                        ldsm4(ah[nxt][mt], smB + X_OFF + aOff + mt * (16 * SX) + akb);
#pragma unroll
                    for (int ntp = 0; ntp < 2; ntp++) {
                        uint32_t r4[4];
                        ldsm4(r4, eB + bOff + ntp * (16 * SE) + (uint32_t)(ks + 1) * 32);
                        bf[nxt][ntp * 2][0] = r4[0]; bf[nxt][ntp * 2][1] = r4[1];
                        bf[nxt][ntp * 2 + 1][0] = r4[2]; bf[nxt][ntp * 2 + 1][1] = r4[3];
                    }
                }
#pragma unroll
                for (int mt = 0; mt < 4; mt++)
#pragma unroll
                    for (int nt = 0; nt < 4; nt++)
                        mma_f16(acc[mt][nt], ah[cur][mt], bf[cur][nt]);
            }
        }

        // ---- epilogue: min-tree per tr + guarded exact insert ----
        {
            const int cb0 = t * 128 + warp_n * 32 + 2 * l2;
            float2 e01[4];
#pragma unroll
            for (int nt = 0; nt < 4; nt++)
                e01[nt] = *(const float2*)(sm + EN_OFF + (cb0 + nt * 8) * 4);

#pragma unroll
            for (int mt = 0; mt < 4; mt++)
#pragma unroll
            for (int h = 0; h < 2; h++) {
                int tr = mt * 2 + h;
                float s[8];
#pragma unroll
                for (int nt = 0; nt < 4; nt++) {
                    s[nt * 2 + 0] = fmaf(-2.f, acc[mt][nt][h * 2 + 0], e01[nt].x);
                    s[nt * 2 + 1] = fmaf(-2.f, acc[mt][nt][h * 2 + 1], e01[nt].y);
                }
                float m = fminf(fminf(fminf(s[0], s[1]), fminf(s[2], s[3])),
                                fminf(fminf(s[4], s[5]), fminf(s[6], s[7])));
                if (m < V2[tr]) {
                    int off = 0;
#pragma unroll
                    for (int j = 7; j >= 1; j--)
                        if (s[j] == m) off = j;     // lowest j wins
                    int code = cb0 + (off >> 1) * 8 + (off & 1);
                    t2x(m, code, V1[tr], I1[tr], V2[tr], I2[tr]);
                }
            }
        }
    }

    // ---- merge across the 4 lanes sharing each row ----
    __syncthreads();   // E ring no longer needed; reuse as scratch
#pragma unroll
    for (int tr = 0; tr < 8; tr++) {
        float v1 = V1[tr], v2 = V2[tr];
        int   i1 = I1[tr], i2 = I2[tr];
#pragma unroll
        for (int o = 1; o <= 2; o <<= 1) {
            float w1 = __shfl_xor_sync(0xFFFFFFFFu, v1, o);
            float w2 = __shfl_xor_sync(0xFFFFFFFFu, v2, o);
            int   j1 = __shfl_xor_sync(0xFFFFFFFFu, i1, o);
            int   j2 = __shfl_xor_sync(0xFFFFFFFFu, i2, o);
            t2_ins(v1, i1, v2, i2, w1, j1);
            t2_ins(v1, i1, v2, i2, w2, j2);
        }
        if (l2 == 0) {
            int mt = tr >> 1, h = tr & 1;
            int rloc = warp_m * 64 + mt * 16 + h * 8 + (lane >> 2);
            uint4 pk;
            pk.x = __float_as_uint(v1); pk.y = (uint32_t)i1;
            pk.z = __float_as_uint(v2); pk.w = (uint32_t)i2;
            *(uint4*)(sm + E_OFF + (rloc * 4 + warp_n) * 16) = pk;
        }
    }
    __syncthreads();

    // ---- final per-row merge over 4 N-warps ----
    if (tid < ROWTILE) {
        float v1 = 3.4e38f, v2 = 3.4e38f;
        int   i1 = 0, i2 = 0;
#pragma unroll
        for (int w = 0; w < 4; w++) {
            uint4 pk = *(const uint4*)(sm + E_OFF + (tid * 4 + w) * 16);
            t2_ins(v1, i1, v2, i2, __uint_as_float(pk.x), (int)pk.y);
            t2_ins(v1, i1, v2, i2, __uint_as_float(pk.z), (int)pk.w);
        }
        g_i1[row0 + tid] = i1;
        g_i2[row0 + tid] = i2;
    }
}

// ------------------------- exact fixup + output + loss ----------------------
__global__ __launch_bounds__(256, 4)
void vq_fixup_kernel(const float* __restrict__ x, const float* __restrict__ emb,
                     float* __restrict__ out) {
    __shared__ float werr[FIXWARPS];
    int wid = threadIdx.x >> 5, lane = threadIdx.x & 31;
    int row = blockIdx.x * FIXWARPS + wid;

    const float4* xr = (const float4*)(x + (size_t)row * DDIM) + lane * 2;
    float4 xa = xr[0], xb = xr[1];
    xa.x = fminf(fmaxf(xa.x, -1.f), 1.f); xa.y = fminf(fmaxf(xa.y, -1.f), 1.f);
    xa.z = fminf(fmaxf(xa.z, -1.f), 1.f); xa.w = fminf(fmaxf(xa.w, -1.f), 1.f);
    xb.x = fminf(fmaxf(xb.x, -1.f), 1.f); xb.y = fminf(fmaxf(xb.y, -1.f), 1.f);
    xb.z = fminf(fmaxf(xb.z, -1.f), 1.f); xb.w = fminf(fmaxf(xb.w, -1.f), 1.f);

    int i1 = g_i1[row], i2 = g_i2[row];
    const float4* e1r = (const float4*)(emb + (size_t)i1 * DDIM) + lane * 2;
    const float4* e2r = (const float4*)(emb + (size_t)i2 * DDIM) + lane * 2;
    float4 e1a = e1r[0], e1b = e1r[1];
    float4 e2a = e2r[0], e2b = e2r[1];

    float p1 = 0.f, p2 = 0.f;
#define ACC(p, ev, xv) p = fmaf(ev, ev, p); p = fmaf(-2.f * (xv), ev, p)
    ACC(p1, e1a.x, xa.x); ACC(p1, e1a.y, xa.y); ACC(p1, e1a.z, xa.z); ACC(p1, e1a.w, xa.w);
    ACC(p1, e1b.x, xb.x); ACC(p1, e1b.y, xb.y); ACC(p1, e1b.z, xb.z); ACC(p1, e1b.w, xb.w);
    ACC(p2, e2a.x, xa.x); ACC(p2, e2a.y, xa.y); ACC(p2, e2a.z, xa.z); ACC(p2, e2a.w, xa.w);
    ACC(p2, e2b.x, xb.x); ACC(p2, e2b.y, xb.y); ACC(p2, e2b.z, xb.z); ACC(p2, e2b.w, xb.w);
#undef ACC
#pragma unroll
    for (int o = 16; o > 0; o >>= 1) {
        p1 += __shfl_xor_sync(0xFFFFFFFFu, p1, o);
        p2 += __shfl_xor_sync(0xFFFFFFFFu, p2, o);
    }
    bool use2 = (p2 < p1) || (p2 == p1 && i2 < i1);
    float4 qa = use2 ? e2a : e1a;
    float4 qb = use2 ? e2b : e1b;

    float err = 0.f;
    float4 oa, ob, d;
    d.x = qa.x - xa.x; d.y = qa.y - xa.y; d.z = qa.z - xa.z; d.w = qa.w - xa.w;
    oa.x = xa.x + d.x; oa.y = xa.y + d.y; oa.z = xa.z + d.z; oa.w = xa.w + d.w;
    err += d.x * d.x + d.y * d.y + d.z * d.z + d.w * d.w;
    d.x = qb.x - xb.x; d.y = qb.y - xb.y; d.z = qb.z - xb.z; d.w = qb.w - xb.w;
    ob.x = xb.x + d.x; ob.y = xb.y + d.y; ob.z = xb.z + d.z; ob.w = xb.w + d.w;
    err += d.x * d.x + d.y * d.y + d.z * d.z + d.w * d.w;

    float4* orow = (float4*)(out + (size_t)row * DDIM) + lane * 2;
    orow[0] = oa;
    orow[1] = ob;

#pragma unroll
    for (int o = 16; o > 0; o >>= 1) err += __shfl_xor_sync(0xFFFFFFFFu, err, o);
    if (lane == 0) werr[wid] = err;
    __syncthreads();
    if (threadIdx.x == 0) {
        float s = 0.f;
#pragma unroll
        for (int w = 0; w < FIXWARPS; w++) s += werr[w];
        g_part[blockIdx.x] = s;
    }
}

__global__ void vq_loss_kernel(float* __restrict__ out, int ND, int out_size) {
    __shared__ float red[256];
    int tid = threadIdx.x;
    float s = 0.f;
    for (int i = tid; i < FIXBLOCKS; i += 256) s += g_part[i];
    red[tid] = s;
    __syncthreads();
    for (int st = 128; st > 0; st >>= 1) {
        if (tid < st) red[tid] += red[tid + st];
        __syncthreads();
    }
    if (tid == 0 && out_size > ND) out[ND] = 1.25f * (red[0] / (float)ND);
    for (int i = ND + 1 + tid; i < out_size; i += 256) out[i] = 0.f;
}

// ---------------------------------- launch ----------------------------------
extern "C" void kernel_launch(void* const* d_in, const int* in_sizes, int n_in,
                              void* d_out, int out_size) {
    const float* x   = (const float*)d_in[0];
    const float* emb = (const float*)d_in[1];
    float* out = (float*)d_out;
    int ND = in_sizes[0];

    cudaFuncSetAttribute(vq_main_kernel,
                         cudaFuncAttributeMaxDynamicSharedMemorySize, SMEM_DYN);

    vq_conv_x<<<(NROWS * DDIM / 4) / 256, 256>>>((const float4*)x, NROWS * DDIM / 4);
    vq_conv_e<<<(KCODES * DDIM / 4) / 256, 256>>>((const float4*)emb, KCODES * DDIM / 4);
    vq_enorm_kernel<<<KCODES / 256, 256>>>(emb, KCODES);
    vq_main_kernel<<<NCTAS, THREADS, SMEM_DYN>>>();
    vq_fixup_kernel<<<FIXBLOCKS, 256>>>(x, emb, out);
    vq_loss_kernel<<<1, 256>>>(out, ND, out_size);
}

// round 16
// speedup vs baseline: 1.1976x; 1.1976x over previous
#include <cuda_runtime.h>
#include <cuda_fp16.h>
#include <cstdint>

// ===========================================================================
// VectorQuantizer on GB300 (sm_103 family): single-pass fp16 distance GEMM
// (fp32 accum) + hierarchical exact top-2 argmin, exact fp32 fixup.
// R16: per-warp PRIVATE E rings (producer == consumer warp) -> ZERO
// __syncthreads in the mainloop; warps decouple so epilogue/preload of one
// warp overlaps MMAs of others. 8 warps, 2x4 grid, warp tile 64x32.
// ===========================================================================

#define NROWS    32768
#define DDIM     256
#define KCODES   8192
#define ROWTILE  128
#define NCTAS    (NROWS / ROWTILE)      // 256
#define NTILES   (KCODES / 128)         // 64
#define NCH      (NTILES * 4)           // 256 chunks (64 k each)
#define THREADS  256
#define FIXWARPS 8
#define FIXBLOCKS (NROWS / FIXWARPS)    // 4096

// SMEM layout (bytes):
//   X [128][264] fp16 @ 0            (row stride 528B)   67584
//   enorm @ 67584  (8192 f32)                            32768
//   E rings @ 100352: warp w at +w*13824, stage s at +s*4608
//       slice = 32 codes x 64k fp16, row stride 144B (128B data + 16 pad)
#define X_OFF     0
#define EN_OFF    67584
#define E_OFF     100352
#define WRING     13824
#define ESTAGE    4608
#define SMEM_DYN  210944
#define SX        528
#define SE        144

__device__ unsigned short g_Xf[NROWS * DDIM];
__device__ unsigned short g_Ef[KCODES * DDIM];
__device__ float g_enorm[KCODES];
__device__ int   g_i1[NROWS];
__device__ int   g_i2[NROWS];
__device__ float g_part[FIXBLOCKS];

// ------------------------------ PTX helpers ---------------------------------
__device__ __forceinline__ uint32_t smem_u32(const void* p) {
    uint32_t a;
    asm("{ .reg .u64 t; cvta.to.shared.u64 t, %1; cvt.u32.u64 %0, t; }"
        : "=r"(a) : "l"(p));
    return a;
}

__device__ __forceinline__ void ldsm4(uint32_t* r, uint32_t addr) {
    asm volatile("ldmatrix.sync.aligned.m8n8.x4.shared.b16 {%0,%1,%2,%3}, [%4];"
                 : "=r"(r[0]), "=r"(r[1]), "=r"(r[2]), "=r"(r[3]) : "r"(addr));
}

__device__ __forceinline__ void mma_f16(float* d, const uint32_t* a,
                                        const uint32_t* b) {
    asm volatile(
        "mma.sync.aligned.m16n8k16.row.col.f32.f16.f16.f32 "
        "{%0,%1,%2,%3}, {%4,%5,%6,%7}, {%8,%9}, {%0,%1,%2,%3};"
        : "+f"(d[0]), "+f"(d[1]), "+f"(d[2]), "+f"(d[3])
        : "r"(a[0]), "r"(a[1]), "r"(a[2]), "r"(a[3]), "r"(b[0]), "r"(b[1]));
}

__device__ __forceinline__ void cpasync16(uint32_t dst, const void* src) {
    asm volatile("cp.async.cg.shared.global [%0], [%1], 16;"
                 :: "r"(dst), "l"(src));
}
#define CP_COMMIT() asm volatile("cp.async.commit_group;" ::: "memory")
#define CP_WAIT0()  asm volatile("cp.async.wait_group 0;" ::: "memory")
#define CP_WAIT1()  asm volatile("cp.async.wait_group 1;" ::: "memory")

// EXACT branchless top-2 insert (fp32 compares, separate index).
__device__ __forceinline__ void t2x(float s, int i,
                                    float& V1, int& I1, float& V2, int& I2) {
    bool lt1 = s < V1;
    bool lt2 = s < V2;
    float nV2 = lt1 ? V1 : (lt2 ? s : V2);
    int   nI2 = lt1 ? I1 : (lt2 ? i : I2);
    V1 = lt1 ? s : V1;
    I1 = lt1 ? i : I1;
    V2 = nV2; I2 = nI2;
}

// tie-aware insert for final merges (prefers lower index on equal value)
__device__ __forceinline__ void t2_ins(float& v1, int& i1, float& v2, int& i2,
                                       float v, int i) {
    if (v < v1 || (v == v1 && i < i1)) { v2 = v1; i2 = i1; v1 = v; i1 = i; }
    else if (v < v2 || (v == v2 && i < i2)) { v2 = v; i2 = i; }
}

// ------------------------------- prep kernels -------------------------------
__global__ void vq_conv_x(const float4* __restrict__ in, int n4) {
    int i = blockIdx.x * blockDim.x + threadIdx.x;
    if (i >= n4) return;
    float4 v = in[i];
    float f[4] = {fminf(fmaxf(v.x, -1.f), 1.f), fminf(fmaxf(v.y, -1.f), 1.f),
                  fminf(fmaxf(v.z, -1.f), 1.f), fminf(fmaxf(v.w, -1.f), 1.f)};
    unsigned short h[4];
#pragma unroll
    for (int j = 0; j < 4; j++) h[j] = __half_as_ushort(__float2half_rn(f[j]));
    ((uint2*)g_Xf)[i] = make_uint2(h[0] | ((uint32_t)h[1] << 16),
                                   h[2] | ((uint32_t)h[3] << 16));
}

__global__ void vq_conv_e(const float4* __restrict__ in, int n4) {
    int i = blockIdx.x * blockDim.x + threadIdx.x;
    if (i >= n4) return;
    float4 v = in[i];
    float f[4] = {v.x, v.y, v.z, v.w};
    unsigned short h[4];
#pragma unroll
    for (int j = 0; j < 4; j++) h[j] = __half_as_ushort(__float2half_rn(f[j]));
    ((uint2*)g_Ef)[i] = make_uint2(h[0] | ((uint32_t)h[1] << 16),
                                   h[2] | ((uint32_t)h[3] << 16));
}

__global__ void vq_enorm_kernel(const float* __restrict__ emb, int K) {
    int k = blockIdx.x * blockDim.x + threadIdx.x;
    if (k >= K) return;
    const float4* r = (const float4*)(emb + (size_t)k * DDIM);
    float s = 0.0f;
#pragma unroll
    for (int i = 0; i < DDIM / 4; i++) {
        float4 v = r[i];
        s += v.x * v.x + v.y * v.y + v.z * v.z + v.w * v.w;
    }
    g_enorm[k] = s;
}

// --------------------------------- main kernel ------------------------------
__global__ __launch_bounds__(THREADS, 1)
void vq_main_kernel() {
    extern __shared__ char sm[];
    const uint32_t smB = smem_u32(sm);

    const int tid   = threadIdx.x;
    const int lane  = tid & 31;
    const int wid   = tid >> 5;
    const int warp_m = wid & 1;         // 0..1 (64 rows each)
    const int warp_n = wid >> 1;        // 0..3 (32 codes each)
    const int l2    = lane & 3;
    const int row0  = blockIdx.x * ROWTILE;

    // ---- resident X tile + enorm into smem (one-time block sync) ----
    {
        const uint4* px = (const uint4*)g_Xf + (size_t)row0 * 32;
        for (int i = tid; i < 4096; i += THREADS) {
            int r = i >> 5, q = i & 31;
            *(uint4*)(sm + X_OFF + r * SX + q * 16) = px[r * 32 + q];
        }
        const float4* pe = (const float4*)g_enorm;
        for (int i = tid; i < 2048; i += THREADS)
            *(float4*)(sm + EN_OFF + i * 16) = pe[i];
    }
    __syncthreads();

    // ---- per-warp private E-slice ring: 32 codes x 64 k, 3 stages ----
    const uint32_t ringB = smB + E_OFF + (uint32_t)wid * WRING;
    auto issueE = [&](int stage, int chunk) {
        int t = chunk >> 2, kc = chunk & 3;
        // slice: 32 rows (codes) x 128B; 256 16B-units; lane does 8
#pragma unroll
        for (int j = 0; j < 8; j++) {
            int u = lane + j * 32;
            int r = u >> 3, q = u & 7;
            size_t soff = ((size_t)(t * 128 + warp_n * 32 + r) * DDIM
                           + kc * 64 + q * 8) * 2;
            uint32_t dst = ringB + stage * ESTAGE + r * SE + q * 16;
            cpasync16(dst, (const char*)g_Ef + soff);
        }
        CP_COMMIT();
    };

    issueE(0, 0);
    issueE(1, 1);

    const uint32_t aOff = (uint32_t)(warp_m * 64 + (lane & 15)) * SX
                        + ((lane >> 4) << 4);
    // B within private slice: code-in-slice = (lane&7) + ((lane>>4)<<3)
    const uint32_t bOff = (uint32_t)((lane & 7) + ((lane >> 4) << 3)) * SE
                        + (((lane >> 3) & 1) << 4);

    float acc[4][4][4];               // [mt][nt][frag]
    float V1[8], V2[8];
    int   I1[8], I2[8];
#pragma unroll
    for (int r = 0; r < 8; r++) {
        V1[r] = 3.4e38f; V2[r] = 3.4e38f; I1[r] = 0; I2[r] = 0;
    }

    uint32_t ah[2][4][4];             // [buf][mt][frag]
    uint32_t bf[2][4][2];             // [buf][nt][frag]

    int stage = 0;
    for (int t = 0; t < NTILES; ++t) {
#pragma unroll
        for (int mt = 0; mt < 4; mt++)
#pragma unroll
            for (int nt = 0; nt < 4; nt++)
#pragma unroll
                for (int rr = 0; rr < 4; rr++) acc[mt][nt][rr] = 0.f;

        for (int kc = 0; kc < 4; ++kc) {
            int idx = t * 4 + kc;
            if (idx + 1 < NCH) { CP_WAIT1(); } else { CP_WAIT0(); }
            __syncwarp();
            if (idx + 2 < NCH) {
                int s2 = stage + 2; if (s2 >= 3) s2 -= 3;
                issueE(s2, idx + 2);
            }

            const uint32_t eB = ringB + stage * ESTAGE;
            stage = (stage == 2) ? 0 : stage + 1;
            const uint32_t akb0 = (uint32_t)(kc * 64) * 2;

            // preload ks=0 fragments into buf 0
#pragma unroll
            for (int mt = 0; mt < 4; mt++)
                ldsm4(ah[0][mt], smB + X_OFF + aOff + mt * (16 * SX) + akb0);
#pragma unroll
            for (int ntp = 0; ntp < 2; ntp++) {
                uint32_t r4[4];
                ldsm4(r4, eB + bOff + ntp * (16 * SE));
                bf[0][ntp * 2][0] = r4[0]; bf[0][ntp * 2][1] = r4[1];
                bf[0][ntp * 2 + 1][0] = r4[2]; bf[0][ntp * 2 + 1][1] = r4[3];
            }

#pragma unroll
            for (int ks = 0; ks < 4; ++ks) {      // k16 steps in 64-k chunk
                const int cur = ks & 1, nxt = cur ^ 1;
                if (ks < 3) {
                    const uint32_t akb = akb0 + (uint32_t)(ks + 1) * 32;
#pragma unroll
                    for (int mt = 0; mt < 4; mt++)
                        ldsm4(ah[nxt][mt], smB + X_OFF + aOff + mt * (16 * SX) + akb);
#pragma unroll
                    for (int ntp = 0; ntp < 2; ntp++) {
                        uint32_t r4[4];
                        ldsm4(r4, eB + bOff + ntp * (16 * SE) + (uint32_t)(ks + 1) * 32);
                        bf[nxt][ntp * 2][0] = r4[0]; bf[nxt][ntp * 2][1] = r4[1];
                        bf[nxt][ntp * 2 + 1][0] = r4[2]; bf[nxt][ntp * 2 + 1][1] = r4[3];
                    }
                }
#pragma unroll
                for (int mt = 0; mt < 4; mt++)
#pragma unroll
                    for (int nt = 0; nt < 4; nt++)
                        mma_f16(acc[mt][nt], ah[cur][mt], bf[cur][nt]);
            }
        }

        // ---- epilogue: min-tree per tr + guarded exact insert ----
        {
            const int cb0 = t * 128 + warp_n * 32 + 2 * l2;
            float2 e01[4];
#pragma unroll
            for (int nt = 0; nt < 4; nt++)
                e01[nt] = *(const float2*)(sm + EN_OFF + (cb0 + nt * 8) * 4);

#pragma unroll
            for (int mt = 0; mt < 4; mt++)
#pragma unroll
            for (int h = 0; h < 2; h++) {
                int tr = mt * 2 + h;
                float s[8];
#pragma unroll
                for (int nt = 0; nt < 4; nt++) {
                    s[nt * 2 + 0] = fmaf(-2.f, acc[mt][nt][h * 2 + 0], e01[nt].x);
                    s[nt * 2 + 1] = fmaf(-2.f, acc[mt][nt][h * 2 + 1], e01[nt].y);
                }
                float m = fminf(fminf(fminf(s[0], s[1]), fminf(s[2], s[3])),
                                fminf(fminf(s[4], s[5]), fminf(s[6], s[7])));
                if (m < V2[tr]) {
                    int off = 0;
#pragma unroll
                    for (int j = 7; j >= 1; j--)
                        if (s[j] == m) off = j;     // lowest j wins
                    int code = cb0 + (off >> 1) * 8 + (off & 1);
                    t2x(m, code, V1[tr], I1[tr], V2[tr], I2[tr]);
                }
            }
        }
    }

    // ---- merge across the 4 lanes sharing each row ----
    __syncthreads();   // mainloop done; E region becomes scratch
#pragma unroll
    for (int tr = 0; tr < 8; tr++) {
        float v1 = V1[tr], v2 = V2[tr];
        int   i1 = I1[tr], i2 = I2[tr];
#pragma unroll
        for (int o = 1; o <= 2; o <<= 1) {
            float w1 = __shfl_xor_sync(0xFFFFFFFFu, v1, o);
            float w2 = __shfl_xor_sync(0xFFFFFFFFu, v2, o);
            int   j1 = __shfl_xor_sync(0xFFFFFFFFu, i1, o);
            int   j2 = __shfl_xor_sync(0xFFFFFFFFu, i2, o);
            t2_ins(v1, i1, v2, i2, w1, j1);
            t2_ins(v1, i1, v2, i2, w2, j2);
        }
        if (l2 == 0) {
            int mt = tr >> 1, h = tr & 1;
            int rloc = warp_m * 64 + mt * 16 + h * 8 + (lane >> 2);
            uint4 pk;
            pk.x = __float_as_uint(v1); pk.y = (uint32_t)i1;
            pk.z = __float_as_uint(v2); pk.w = (uint32_t)i2;
            *(uint4*)(sm + E_OFF + (rloc * 4 + warp_n) * 16) = pk;
        }
    }
    __syncthreads();

    // ---- final per-row merge over 4 N-warps ----
    if (tid < ROWTILE) {
        float v1 = 3.4e38f, v2 = 3.4e38f;
        int   i1 = 0, i2 = 0;
#pragma unroll
        for (int w = 0; w < 4; w++) {
            uint4 pk = *(const uint4*)(sm + E_OFF + (tid * 4 + w) * 16);
            t2_ins(v1, i1, v2, i2, __uint_as_float(pk.x), (int)pk.y);
            t2_ins(v1, i1, v2, i2, __uint_as_float(pk.z), (int)pk.w);
        }
        g_i1[row0 + tid] = i1;
        g_i2[row0 + tid] = i2;
    }
}

// ------------------------- exact fixup + output + loss ----------------------
__global__ __launch_bounds__(256, 4)
void vq_fixup_kernel(const float* __restrict__ x, const float* __restrict__ emb,
                     float* __restrict__ out) {
    __shared__ float werr[FIXWARPS];
    int wid = threadIdx.x >> 5, lane = threadIdx.x & 31;
    int row = blockIdx.x * FIXWARPS + wid;

    const float4* xr = (const float4*)(x + (size_t)row * DDIM) + lane * 2;
    float4 xa = xr[0], xb = xr[1];
    xa.x = fminf(fmaxf(xa.x, -1.f), 1.f); xa.y = fminf(fmaxf(xa.y, -1.f), 1.f);
    xa.z = fminf(fmaxf(xa.z, -1.f), 1.f); xa.w = fminf(fmaxf(xa.w, -1.f), 1.f);
    xb.x = fminf(fmaxf(xb.x, -1.f), 1.f); xb.y = fminf(fmaxf(xb.y, -1.f), 1.f);
    xb.z = fminf(fmaxf(xb.z, -1.f), 1.f); xb.w = fminf(fmaxf(xb.w, -1.f), 1.f);

    int i1 = g_i1[row], i2 = g_i2[row];
    const float4* e1r = (const float4*)(emb + (size_t)i1 * DDIM) + lane * 2;
    const float4* e2r = (const float4*)(emb + (size_t)i2 * DDIM) + lane * 2;
    float4 e1a = e1r[0], e1b = e1r[1];
    float4 e2a = e2r[0], e2b = e2r[1];

    float p1 = 0.f, p2 = 0.f;
#define ACC(p, ev, xv) p = fmaf(ev, ev, p); p = fmaf(-2.f * (xv), ev, p)
    ACC(p1, e1a.x, xa.x); ACC(p1, e1a.y, xa.y); ACC(p1, e1a.z, xa.z); ACC(p1, e1a.w, xa.w);
    ACC(p1, e1b.x, xb.x); ACC(p1, e1b.y, xb.y); ACC(p1, e1b.z, xb.z); ACC(p1, e1b.w, xb.w);
    ACC(p2, e2a.x, xa.x); ACC(p2, e2a.y, xa.y); ACC(p2, e2a.z, xa.z); ACC(p2, e2a.w, xa.w);
    ACC(p2, e2b.x, xb.x); ACC(p2, e2b.y, xb.y); ACC(p2, e2b.z, xb.z); ACC(p2, e2b.w, xb.w);
#undef ACC
#pragma unroll
    for (int o = 16; o > 0; o >>= 1) {
        p1 += __shfl_xor_sync(0xFFFFFFFFu, p1, o);
        p2 += __shfl_xor_sync(0xFFFFFFFFu, p2, o);
    }
    bool use2 = (p2 < p1) || (p2 == p1 && i2 < i1);
    float4 qa = use2 ? e2a : e1a;
    float4 qb = use2 ? e2b : e1b;

    float err = 0.f;
    float4 oa, ob, d;
    d.x = qa.x - xa.x; d.y = qa.y - xa.y; d.z = qa.z - xa.z; d.w = qa.w - xa.w;
    oa.x = xa.x + d.x; oa.y = xa.y + d.y; oa.z = xa.z + d.z; oa.w = xa.w + d.w;
    err += d.x * d.x + d.y * d.y + d.z * d.z + d.w * d.w;
    d.x = qb.x - xb.x; d.y = qb.y - xb.y; d.z = qb.z - xb.z; d.w = qb.w - xb.w;
    ob.x = xb.x + d.x; ob.y = xb.y + d.y; ob.z = xb.z + d.z; ob.w = xb.w + d.w;
    err += d.x * d.x + d.y * d.y + d.z * d.z + d.w * d.w;

    float4* orow = (float4*)(out + (size_t)row * DDIM) + lane * 2;
    orow[0] = oa;
    orow[1] = ob;

#pragma unroll
    for (int o = 16; o > 0; o >>= 1) err += __shfl_xor_sync(0xFFFFFFFFu, err, o);
    if (lane == 0) werr[wid] = err;
    __syncthreads();
    if (threadIdx.x == 0) {
        float s = 0.f;
#pragma unroll
        for (int w = 0; w < FIXWARPS; w++) s += werr[w];
        g_part[blockIdx.x] = s;
    }
}

__global__ void vq_loss_kernel(float* __restrict__ out, int ND, int out_size) {
    __shared__ float red[256];
    int tid = threadIdx.x;
    float s = 0.f;
    for (int i = tid; i < FIXBLOCKS; i += 256) s += g_part[i];
    red[tid] = s;
    __syncthreads();
    for (int st = 128; st > 0; st >>= 1) {
        if (tid < st) red[tid] += red[tid + st];
        __syncthreads();
    }
    if (tid == 0 && out_size > ND) out[ND] = 1.25f * (red[0] / (float)ND);
    for (int i = ND + 1 + tid; i < out_size; i += 256) out[i] = 0.f;
}

// ---------------------------------- launch ----------------------------------
extern "C" void kernel_launch(void* const* d_in, const int* in_sizes, int n_in,
                              void* d_out, int out_size) {
    const float* x   = (const float*)d_in[0];
    const float* emb = (const float*)d_in[1];
    float* out = (float*)d_out;
    int ND = in_sizes[0];

    cudaFuncSetAttribute(vq_main_kernel,
                         cudaFuncAttributeMaxDynamicSharedMemorySize, SMEM_DYN);

    vq_conv_x<<<(NROWS * DDIM / 4) / 256, 256>>>((const float4*)x, NROWS * DDIM / 4);
    vq_conv_e<<<(KCODES * DDIM / 4) / 256, 256>>>((const float4*)emb, KCODES * DDIM / 4);
    vq_enorm_kernel<<<KCODES / 256, 256>>>(emb, KCODES);
    vq_main_kernel<<<NCTAS, THREADS, SMEM_DYN>>>();
    vq_fixup_kernel<<<FIXBLOCKS, 256>>>(x, emb, out);
    vq_loss_kernel<<<1, 256>>>(out, ND, out_size);
}

// round 17
// speedup vs baseline: 1.2815x; 1.0701x over previous
#include <cuda_runtime.h>
#include <cuda_fp16.h>
#include <cstdint>

// ===========================================================================
// VectorQuantizer on GB300 (sm_103 family): single-pass fp16 distance GEMM
// (fp32 accum) + hierarchical exact top-2 argmin, exact fp32 fixup.
// R17: 16 warps (4x4 grid) + GROUP-SHARED 3-stage E rings. The 4 warps of a
// warp_n group share one ring and sync via a named barrier (bar.sync id,128)
// -- no block-wide __syncthreads in the mainloop; groups fully decoupled.
// ===========================================================================

#define NROWS    32768
#define DDIM     256
#define KCODES   8192
#define ROWTILE  128
#define NCTAS    (NROWS / ROWTILE)      // 256
#define NTILES   (KCODES / 128)         // 64
#define NCH      (NTILES * 4)           // 256 chunks (64 k each)
#define THREADS  512
#define FIXWARPS 8
#define FIXBLOCKS (NROWS / FIXWARPS)    // 4096

// SMEM layout (bytes):
//   X [128][264] fp16 @ 0            (row stride 528B)   67584
//   enorm @ 67584  (8192 f32)                            32768
//   E rings @ 100352: group g (=warp_n) at +g*13824, stage s at +s*4608
//       slice = 32 codes x 64k fp16, row stride 144B
#define X_OFF     0
#define EN_OFF    67584
#define E_OFF     100352
#define GRING     13824
#define ESTAGE    4608
#define SMEM_DYN  155648
#define SX        528
#define SE        144

__device__ unsigned short g_Xf[NROWS * DDIM];
__device__ unsigned short g_Ef[KCODES * DDIM];
__device__ float g_enorm[KCODES];
__device__ int   g_i1[NROWS];
__device__ int   g_i2[NROWS];
__device__ float g_part[FIXBLOCKS];

// ------------------------------ PTX helpers ---------------------------------
__device__ __forceinline__ uint32_t smem_u32(const void* p) {
    uint32_t a;
    asm("{ .reg .u64 t; cvta.to.shared.u64 t, %1; cvt.u32.u64 %0, t; }"
        : "=r"(a) : "l"(p));
    return a;
}

__device__ __forceinline__ void ldsm4(uint32_t* r, uint32_t addr) {
    asm volatile("ldmatrix.sync.aligned.m8n8.x4.shared.b16 {%0,%1,%2,%3}, [%4];"
                 : "=r"(r[0]), "=r"(r[1]), "=r"(r[2]), "=r"(r[3]) : "r"(addr));
}

__device__ __forceinline__ void mma_f16(float* d, const uint32_t* a,
                                        const uint32_t* b) {
    asm volatile(
        "mma.sync.aligned.m16n8k16.row.col.f32.f16.f16.f32 "
        "{%0,%1,%2,%3}, {%4,%5,%6,%7}, {%8,%9}, {%0,%1,%2,%3};"
        : "+f"(d[0]), "+f"(d[1]), "+f"(d[2]), "+f"(d[3])
        : "r"(a[0]), "r"(a[1]), "r"(a[2]), "r"(a[3]), "r"(b[0]), "r"(b[1]));
}

__device__ __forceinline__ void cpasync16(uint32_t dst, const void* src) {
    asm volatile("cp.async.cg.shared.global [%0], [%1], 16;"
                 :: "r"(dst), "l"(src));
}
#define CP_COMMIT() asm volatile("cp.async.commit_group;" ::: "memory")
#define CP_WAIT0()  asm volatile("cp.async.wait_group 0;" ::: "memory")
#define CP_WAIT1()  asm volatile("cp.async.wait_group 1;" ::: "memory")
#define NAMED_BAR(id) \
    asm volatile("bar.sync %0, 128;" :: "r"(id) : "memory")

// EXACT branchless top-2 insert (fp32 compares, separate index).
__device__ __forceinline__ void t2x(float s, int i,
                                    float& V1, int& I1, float& V2, int& I2) {
    bool lt1 = s < V1;
    bool lt2 = s < V2;
    float nV2 = lt1 ? V1 : (lt2 ? s : V2);
    int   nI2 = lt1 ? I1 : (lt2 ? i : I2);
    V1 = lt1 ? s : V1;
    I1 = lt1 ? i : I1;
    V2 = nV2; I2 = nI2;
}

// tie-aware insert for final merges (prefers lower index on equal value)
__device__ __forceinline__ void t2_ins(float& v1, int& i1, float& v2, int& i2,
                                       float v, int i) {
    if (v < v1 || (v == v1 && i < i1)) { v2 = v1; i2 = i1; v1 = v; i1 = i; }
    else if (v < v2 || (v == v2 && i < i2)) { v2 = v; i2 = i; }
}

// ------------------------------- prep kernels -------------------------------
__global__ void vq_conv_x(const float4* __restrict__ in, int n4) {
    int i = blockIdx.x * blockDim.x + threadIdx.x;
    if (i >= n4) return;
    float4 v = in[i];
    float f[4] = {fminf(fmaxf(v.x, -1.f), 1.f), fminf(fmaxf(v.y, -1.f), 1.f),
                  fminf(fmaxf(v.z, -1.f), 1.f), fminf(fmaxf(v.w, -1.f), 1.f)};
    unsigned short h[4];
#pragma unroll
    for (int j = 0; j < 4; j++) h[j] = __half_as_ushort(__float2half_rn(f[j]));
    ((uint2*)g_Xf)[i] = make_uint2(h[0] | ((uint32_t)h[1] << 16),
                                   h[2] | ((uint32_t)h[3] << 16));
}

__global__ void vq_conv_e(const float4* __restrict__ in, int n4) {
    int i = blockIdx.x * blockDim.x + threadIdx.x;
    if (i >= n4) return;
    float4 v = in[i];
    float f[4] = {v.x, v.y, v.z, v.w};
    unsigned short h[4];
#pragma unroll
    for (int j = 0; j < 4; j++) h[j] = __half_as_ushort(__float2half_rn(f[j]));
    ((uint2*)g_Ef)[i] = make_uint2(h[0] | ((uint32_t)h[1] << 16),
                                   h[2] | ((uint32_t)h[3] << 16));
}

__global__ void vq_enorm_kernel(const float* __restrict__ emb, int K) {
    int k = blockIdx.x * blockDim.x + threadIdx.x;
    if (k >= K) return;
    const float4* r = (const float4*)(emb + (size_t)k * DDIM);
    float s = 0.0f;
#pragma unroll
    for (int i = 0; i < DDIM / 4; i++) {
        float4 v = r[i];
        s += v.x * v.x + v.y * v.y + v.z * v.z + v.w * v.w;
    }
    g_enorm[k] = s;
}

// --------------------------------- main kernel ------------------------------
__global__ __launch_bounds__(THREADS, 1)
void vq_main_kernel() {
    extern __shared__ char sm[];
    const uint32_t smB = smem_u32(sm);

    const int tid   = threadIdx.x;
    const int lane  = tid & 31;
    const int wid   = tid >> 5;
    const int warp_m = wid & 3;         // 0..3 (32 rows each)
    const int warp_n = wid >> 2;        // 0..3 (32 codes each) = ring group
    const int l2    = lane & 3;
    const int gtid  = warp_m * 32 + lane;   // 0..127 within group
    const int barid = 1 + warp_n;
    const int row0  = blockIdx.x * ROWTILE;

    // ---- resident X tile + enorm into smem (one-time block sync) ----
    {
        const uint4* px = (const uint4*)g_Xf + (size_t)row0 * 32;
        for (int i = tid; i < 4096; i += THREADS) {
            int r = i >> 5, q = i & 31;
            *(uint4*)(sm + X_OFF + r * SX + q * 16) = px[r * 32 + q];
        }
        const float4* pe = (const float4*)g_enorm;
        for (int i = tid; i < 2048; i += THREADS)
            *(float4*)(sm + EN_OFF + i * 16) = pe[i];
    }
    __syncthreads();

    // ---- group-shared 3-stage ring: slice = 32 codes x 64 k ----
    const uint32_t ringB = smB + E_OFF + (uint32_t)warp_n * GRING;
    auto issueE = [&](int stage, int chunk) {
        int t = chunk >> 2, kc = chunk & 3;
        // 256 16B-units per stage; 128 group threads -> 2 each
#pragma unroll
        for (int j = 0; j < 2; j++) {
            int u = gtid + j * 128;
            int r = u >> 3, q = u & 7;
            size_t soff = ((size_t)(t * 128 + warp_n * 32 + r) * DDIM
                           + kc * 64 + q * 8) * 2;
            uint32_t dst = ringB + stage * ESTAGE + r * SE + q * 16;
            cpasync16(dst, (const char*)g_Ef + soff);
        }
        CP_COMMIT();
    };

    issueE(0, 0);
    issueE(1, 1);

    const uint32_t aOff = (uint32_t)(warp_m * 32 + (lane & 15)) * SX
                        + ((lane >> 4) << 4);
    const uint32_t bOff = (uint32_t)((lane & 7) + ((lane >> 4) << 3)) * SE
                        + (((lane >> 3) & 1) << 4);

    float acc[2][4][4];               // [mt][nt][frag]
    float V1[4], V2[4];
    int   I1[4], I2[4];
#pragma unroll
    for (int r = 0; r < 4; r++) {
        V1[r] = 3.4e38f; V2[r] = 3.4e38f; I1[r] = 0; I2[r] = 0;
    }

    uint32_t ah[2][2][4];             // [buf][mt][frag]
    uint32_t bf[2][4][2];             // [buf][nt][frag]

    int stage = 0;
    for (int t = 0; t < NTILES; ++t) {
#pragma unroll
        for (int mt = 0; mt < 2; mt++)
#pragma unroll
            for (int nt = 0; nt < 4; nt++)
#pragma unroll
                for (int rr = 0; rr < 4; rr++) acc[mt][nt][rr] = 0.f;

        for (int kc = 0; kc < 4; ++kc) {
            int idx = t * 4 + kc;
            if (idx + 1 < NCH) { CP_WAIT1(); } else { CP_WAIT0(); }
            NAMED_BAR(barid);          // group-scoped: 4 warps only
            if (idx + 2 < NCH) {
                int s2 = stage + 2; if (s2 >= 3) s2 -= 3;
                issueE(s2, idx + 2);
            }

            const uint32_t eB = ringB + stage * ESTAGE;
            stage = (stage == 2) ? 0 : stage + 1;
            const uint32_t akb0 = (uint32_t)(kc * 64) * 2;

            // preload ks=0 fragments into buf 0
#pragma unroll
            for (int mt = 0; mt < 2; mt++)
                ldsm4(ah[0][mt], smB + X_OFF + aOff + mt * (16 * SX) + akb0);
#pragma unroll
            for (int ntp = 0; ntp < 2; ntp++) {
                uint32_t r4[4];
                ldsm4(r4, eB + bOff + ntp * (16 * SE));
                bf[0][ntp * 2][0] = r4[0]; bf[0][ntp * 2][1] = r4[1];
                bf[0][ntp * 2 + 1][0] = r4[2]; bf[0][ntp * 2 + 1][1] = r4[3];
            }

#pragma unroll
            for (int ks = 0; ks < 4; ++ks) {      // k16 steps in 64-k chunk
                const int cur = ks & 1, nxt = cur ^ 1;
                if (ks < 3) {
                    const uint32_t akb = akb0 + (uint32_t)(ks + 1) * 32;
#pragma unroll
                    for (int mt = 0; mt < 2; mt++)
                        ldsm4(ah[nxt][mt], smB + X_OFF + aOff + mt * (16 * SX) + akb);
#pragma unroll
                    for (int ntp = 0; ntp < 2; ntp++) {
                        uint32_t r4[4];
                        ldsm4(r4, eB + bOff + ntp * (16 * SE) + (uint32_t)(ks + 1) * 32);
                        bf[nxt][ntp * 2][0] = r4[0]; bf[nxt][ntp * 2][1] = r4[1];
                        bf[nxt][ntp * 2 + 1][0] = r4[2]; bf[nxt][ntp * 2 + 1][1] = r4[3];
                    }
                }
#pragma unroll
                for (int mt = 0; mt < 2; mt++)
#pragma unroll
                    for (int nt = 0; nt < 4; nt++)
                        mma_f16(acc[mt][nt], ah[cur][mt], bf[cur][nt]);
            }
        }

        // ---- epilogue: min-tree per tr + guarded exact insert ----
        {
            const int cb0 = t * 128 + warp_n * 32 + 2 * l2;
            float2 e01[4];
#pragma unroll
            for (int nt = 0; nt < 4; nt++)
                e01[nt] = *(const float2*)(sm + EN_OFF + (cb0 + nt * 8) * 4);

#pragma unroll
            for (int mt = 0; mt < 2; mt++)
#pragma unroll
            for (int h = 0; h < 2; h++) {
                int tr = mt * 2 + h;
                float s[8];
#pragma unroll
                for (int nt = 0; nt < 4; nt++) {
                    s[nt * 2 + 0] = fmaf(-2.f, acc[mt][nt][h * 2 + 0], e01[nt].x);
                    s[nt * 2 + 1] = fmaf(-2.f, acc[mt][nt][h * 2 + 1], e01[nt].y);
                }
                float m = fminf(fminf(fminf(s[0], s[1]), fminf(s[2], s[3])),
                                fminf(fminf(s[4], s[5]), fminf(s[6], s[7])));
                if (m < V2[tr]) {
                    int off = 0;
#pragma unroll
                    for (int j = 7; j >= 1; j--)
                        if (s[j] == m) off = j;     // lowest j wins
                    int code = cb0 + (off >> 1) * 8 + (off & 1);
                    t2x(m, code, V1[tr], I1[tr], V2[tr], I2[tr]);
                }
            }
        }
    }

    // ---- merge across the 4 lanes sharing each row ----
    __syncthreads();   // mainloop done; E region becomes scratch
#pragma unroll
    for (int tr = 0; tr < 4; tr++) {
        float v1 = V1[tr], v2 = V2[tr];
        int   i1 = I1[tr], i2 = I2[tr];
#pragma unroll
        for (int o = 1; o <= 2; o <<= 1) {
            float w1 = __shfl_xor_sync(0xFFFFFFFFu, v1, o);
            float w2 = __shfl_xor_sync(0xFFFFFFFFu, v2, o);
            int   j1 = __shfl_xor_sync(0xFFFFFFFFu, i1, o);
            int   j2 = __shfl_xor_sync(0xFFFFFFFFu, i2, o);
            t2_ins(v1, i1, v2, i2, w1, j1);
            t2_ins(v1, i1, v2, i2, w2, j2);
        }
        if (l2 == 0) {
            int mt = tr >> 1, h = tr & 1;
            int rloc = warp_m * 32 + mt * 16 + h * 8 + (lane >> 2);
            uint4 pk;
            pk.x = __float_as_uint(v1); pk.y = (uint32_t)i1;
            pk.z = __float_as_uint(v2); pk.w = (uint32_t)i2;
            *(uint4*)(sm + E_OFF + (rloc * 4 + warp_n) * 16) = pk;
        }
    }
    __syncthreads();

    // ---- final per-row merge over 4 N-warps ----
    if (tid < ROWTILE) {
        float v1 = 3.4e38f, v2 = 3.4e38f;
        int   i1 = 0, i2 = 0;
#pragma unroll
        for (int w = 0; w < 4; w++) {
            uint4 pk = *(const uint4*)(sm + E_OFF + (tid * 4 + w) * 16);
            t2_ins(v1, i1, v2, i2, __uint_as_float(pk.x), (int)pk.y);
            t2_ins(v1, i1, v2, i2, __uint_as_float(pk.z), (int)pk.w);
        }
        g_i1[row0 + tid] = i1;
        g_i2[row0 + tid] = i2;
    }
}

// ------------------------- exact fixup + output + loss ----------------------
__global__ __launch_bounds__(256, 4)
void vq_fixup_kernel(const float* __restrict__ x, const float* __restrict__ emb,
                     float* __restrict__ out) {
    __shared__ float werr[FIXWARPS];
    int wid = threadIdx.x >> 5, lane = threadIdx.x & 31;
    int row = blockIdx.x * FIXWARPS + wid;

    const float4* xr = (const float4*)(x + (size_t)row * DDIM) + lane * 2;
    float4 xa = xr[0], xb = xr[1];
    xa.x = fminf(fmaxf(xa.x, -1.f), 1.f); xa.y = fminf(fmaxf(xa.y, -1.f), 1.f);
    xa.z = fminf(fmaxf(xa.z, -1.f), 1.f); xa.w = fminf(fmaxf(xa.w, -1.f), 1.f);
    xb.x = fminf(fmaxf(xb.x, -1.f), 1.f); xb.y = fminf(fmaxf(xb.y, -1.f), 1.f);
    xb.z = fminf(fmaxf(xb.z, -1.f), 1.f); xb.w = fminf(fmaxf(xb.w, -1.f), 1.f);

    int i1 = g_i1[row], i2 = g_i2[row];
    const float4* e1r = (const float4*)(emb + (size_t)i1 * DDIM) + lane * 2;
    const float4* e2r = (const float4*)(emb + (size_t)i2 * DDIM) + lane * 2;
    float4 e1a = e1r[0], e1b = e1r[1];
    float4 e2a = e2r[0], e2b = e2r[1];

    float p1 = 0.f, p2 = 0.f;
#define ACC(p, ev, xv) p = fmaf(ev, ev, p); p = fmaf(-2.f * (xv), ev, p)
    ACC(p1, e1a.x, xa.x); ACC(p1, e1a.y, xa.y); ACC(p1, e1a.z, xa.z); ACC(p1, e1a.w, xa.w);
    ACC(p1, e1b.x, xb.x); ACC(p1, e1b.y, xb.y); ACC(p1, e1b.z, xb.z); ACC(p1, e1b.w, xb.w);
    ACC(p2, e2a.x, xa.x); ACC(p2, e2a.y, xa.y); ACC(p2, e2a.z, xa.z); ACC(p2, e2a.w, xa.w);
    ACC(p2, e2b.x, xb.x); ACC(p2, e2b.y, xb.y); ACC(p2, e2b.z, xb.z); ACC(p2, e2b.w, xb.w);
#undef ACC
#pragma unroll
    for (int o = 16; o > 0; o >>= 1) {
        p1 += __shfl_xor_sync(0xFFFFFFFFu, p1, o);
        p2 += __shfl_xor_sync(0xFFFFFFFFu, p2, o);
    }
    bool use2 = (p2 < p1) || (p2 == p1 && i2 < i1);
    float4 qa = use2 ? e2a : e1a;
    float4 qb = use2 ? e2b : e1b;

    float err = 0.f;
    float4 oa, ob, d;
    d.x = qa.x - xa.x; d.y = qa.y - xa.y; d.z = qa.z - xa.z; d.w = qa.w - xa.w;
    oa.x = xa.x + d.x; oa.y = xa.y + d.y; oa.z = xa.z + d.z; oa.w = xa.w + d.w;
    err += d.x * d.x + d.y * d.y + d.z * d.z + d.w * d.w;
    d.x = qb.x - xb.x; d.y = qb.y - xb.y; d.z = qb.z - xb.z; d.w = qb.w - xb.w;
    ob.x = xb.x + d.x; ob.y = xb.y + d.y; ob.z = xb.z + d.z; ob.w = xb.w + d.w;
    err += d.x * d.x + d.y * d.y + d.z * d.z + d.w * d.w;

    float4* orow = (float4*)(out + (size_t)row * DDIM) + lane * 2;
    orow[0] = oa;
    orow[1] = ob;

#pragma unroll
    for (int o = 16; o > 0; o >>= 1) err += __shfl_xor_sync(0xFFFFFFFFu, err, o);
    if (lane == 0) werr[wid] = err;
    __syncthreads();
    if (threadIdx.x == 0) {
        float s = 0.f;
#pragma unroll
        for (int w = 0; w < FIXWARPS; w++) s += werr[w];
        g_part[blockIdx.x] = s;
    }
}

__global__ void vq_loss_kernel(float* __restrict__ out, int ND, int out_size) {
    __shared__ float red[256];
    int tid = threadIdx.x;
    float s = 0.f;
    for (int i = tid; i < FIXBLOCKS; i += 256) s += g_part[i];
    red[tid] = s;
    __syncthreads();
    for (int st = 128; st > 0; st >>= 1) {
        if (tid < st) red[tid] += red[tid + st];
        __syncthreads();
    }
    if (tid == 0 && out_size > ND) out[ND] = 1.25f * (red[0] / (float)ND);
    for (int i = ND + 1 + tid; i < out_size; i += 256) out[i] = 0.f;
}

// ---------------------------------- launch ----------------------------------
extern "C" void kernel_launch(void* const* d_in, const int* in_sizes, int n_in,
                              void* d_out, int out_size) {
    const float* x   = (const float*)d_in[0];
    const float* emb = (const float*)d_in[1];
    float* out = (float*)d_out;
    int ND = in_sizes[0];

    cudaFuncSetAttribute(vq_main_kernel,
                         cudaFuncAttributeMaxDynamicSharedMemorySize, SMEM_DYN);

    vq_conv_x<<<(NROWS * DDIM / 4) / 256, 256>>>((const float4*)x, NROWS * DDIM / 4);
    vq_conv_e<<<(KCODES * DDIM / 4) / 256, 256>>>((const float4*)emb, KCODES * DDIM / 4);
    vq_enorm_kernel<<<KCODES / 256, 256>>>(emb, KCODES);
    vq_main_kernel<<<NCTAS, THREADS, SMEM_DYN>>>();
    vq_fixup_kernel<<<FIXBLOCKS, 256>>>(x, emb, out);
    vq_loss_kernel<<<1, 256>>>(out, ND, out_size);
}